// round 1
// baseline (speedup 1.0000x reference)
#include <cuda_runtime.h>

// ModelBLA: linear state-space simulation.
//   X_{k+1} = A X_k + B_u U_k ;  Y_k = C_y X_k + D_yu U_k ;  X_0 = 0
// Output = (Y, X) flattened: Y[8192][4][128] then X[8192][64][128], fp32.
//
// Algorithm (exact, fp32):
//   blocks of L=32 steps, M=256 blocks
//   1) k_powers : A^32 (by squaring) and G = [A^31 B, ..., B]  (64 x 128)
//   2) k_fgemm  : f_c = G @ U_c  per block (U_c is the contiguous u slab)
//   3) k_scan   : x_{c+1} = A^32 x_c + f_c   (256 sequential steps, 128 CTAs)
//   4) k_expand : per block, re-run the 32-step recurrence from x_c,
//                 writing X (pre-update) and Y each step.

#define NSTEP 8192
#define NUDIM 4
#define RB    128
#define NXDIM 64
#define NYDIM 4
#define LBLK  32
#define MBLK  (NSTEP / LBLK)   // 256

// scratch (no allocations allowed)
__device__ float g_F [MBLK * RB * NXDIM];   // [c][r][i]  8 MB
__device__ float g_Xs[MBLK * RB * NXDIM];   // [c][r][i]  8 MB
__device__ float g_A32[NXDIM * NXDIM];
__device__ float g_G [NXDIM * (LBLK * NUDIM)];   // [i][4j+q] = (A^{L-1-j} B)[i][q]

// ---------------------------------------------------------------------------
// Kernel 1: A^32 by repeated squaring + G chain. One CTA, 256 threads.
// ---------------------------------------------------------------------------
__global__ void k_powers(const float* __restrict__ A, const float* __restrict__ Bu) {
    __shared__ float Asm[NXDIM * 65];        // padded rows (stride 65) vs bank conflicts
    __shared__ float vb[2][NXDIM * NUDIM];
    int t = threadIdx.x;                      // 256 threads

    for (int idx = t; idx < NXDIM * NXDIM; idx += 256)
        Asm[(idx / NXDIM) * 65 + (idx % NXDIM)] = A[idx];
    vb[0][t] = Bu[t];                         // NXDIM*NUDIM == 256 exactly
    __syncthreads();

    // G columns: G[i][4*(L-1-m)+q] = (A^m B)[i][q]
    int gi = t >> 2, gq = t & 3;
    int cur = 0;
    for (int m = 0; m < LBLK; m++) {
        g_G[gi * (LBLK * NUDIM) + 4 * (LBLK - 1 - m) + gq] = vb[cur][gi * NUDIM + gq];
        float s = 0.f;
        #pragma unroll 8
        for (int k = 0; k < NXDIM; k++)
            s += Asm[gi * 65 + k] * vb[cur][k * NUDIM + gq];
        vb[cur ^ 1][gi * NUDIM + gq] = s;
        cur ^= 1;
        __syncthreads();
    }

    // squarings: A -> A^2 -> A^4 -> A^8 -> A^16 -> A^32 (in place, reg-staged)
    int oi = t >> 2;
    int oj0 = (t & 3) * 16;
    for (int st = 0; st < 5; st++) {
        float accq[16];
        #pragma unroll
        for (int jj = 0; jj < 16; jj++) accq[jj] = 0.f;
        for (int k = 0; k < NXDIM; k++) {
            float a = Asm[oi * 65 + k];
            #pragma unroll
            for (int jj = 0; jj < 16; jj++)
                accq[jj] += a * Asm[k * 65 + oj0 + jj];
        }
        __syncthreads();
        #pragma unroll
        for (int jj = 0; jj < 16; jj++) Asm[oi * 65 + oj0 + jj] = accq[jj];
        __syncthreads();
    }
    for (int idx = t; idx < NXDIM * NXDIM; idx += 256)
        g_A32[idx] = Asm[(idx / NXDIM) * 65 + (idx % NXDIM)];
}

// ---------------------------------------------------------------------------
// Kernel 2: f_c = G (64x128) @ U_c (128x128).  One CTA per block c.
// ---------------------------------------------------------------------------
__global__ void __launch_bounds__(256) k_fgemm(const float* __restrict__ u) {
    extern __shared__ float sm[];
    float* Gt = sm;                      // [k][i]  128*64
    float* Ut = sm + 128 * NXDIM;        // [kk][r] 32*128 chunk
    int t = threadIdx.x;
    int c = blockIdx.x;
    int rb = t & 15, ib = t >> 4;
    int r0 = rb * 8, i0 = ib * 4;

    for (int idx = t; idx < 128 * NXDIM; idx += 256) {
        int i = idx >> 7, k = idx & 127;     // g_G layout [i][k]
        Gt[k * NXDIM + i] = g_G[idx];
    }

    float acc[4][8];
    #pragma unroll
    for (int ii = 0; ii < 4; ii++)
        #pragma unroll
        for (int rr = 0; rr < 8; rr++) acc[ii][rr] = 0.f;

    const float* ublk = u + (size_t)c * (LBLK * NUDIM * RB);   // 128x128 slab
    for (int k0 = 0; k0 < 128; k0 += 32) {
        __syncthreads();
        for (int idx = t; idx < 32 * 128; idx += 256)
            Ut[idx] = ublk[(k0 + (idx >> 7)) * 128 + (idx & 127)];
        __syncthreads();
        #pragma unroll 8
        for (int kk = 0; kk < 32; kk++) {
            float4 g  = *(const float4*)(Gt + (k0 + kk) * NXDIM + i0);
            float4 ua = *(const float4*)(Ut + kk * 128 + r0);
            float4 ub = *(const float4*)(Ut + kk * 128 + r0 + 4);
            float gv[4] = {g.x, g.y, g.z, g.w};
            float uv[8] = {ua.x, ua.y, ua.z, ua.w, ub.x, ub.y, ub.z, ub.w};
            #pragma unroll
            for (int ii = 0; ii < 4; ii++)
                #pragma unroll
                for (int rr = 0; rr < 8; rr++)
                    acc[ii][rr] += gv[ii] * uv[rr];
        }
    }
    float* f = g_F + (size_t)c * (RB * NXDIM);
    #pragma unroll
    for (int rr = 0; rr < 8; rr++) {
        float4 v = make_float4(acc[0][rr], acc[1][rr], acc[2][rr], acc[3][rr]);
        *(float4*)(f + (r0 + rr) * NXDIM + i0) = v;
    }
}

// ---------------------------------------------------------------------------
// Kernel 3: sequential scan over blocks.  One CTA per column r, 64 threads.
//   Xs[c] = x ; x = A^32 x + F[c]
// ---------------------------------------------------------------------------
__global__ void __launch_bounds__(64) k_scan() {
    __shared__ float At[NXDIM * NXDIM];   // [j][i]
    __shared__ float xsh[NXDIM];
    int r = blockIdx.x;
    int i = threadIdx.x;

    for (int idx = i; idx < NXDIM * NXDIM; idx += 64) {
        int ii = idx / NXDIM, jj = idx % NXDIM;
        At[jj * NXDIM + ii] = g_A32[idx];
    }

    const int PF = 4;
    float fbuf[PF];
    #pragma unroll
    for (int p = 0; p < PF; p++)
        fbuf[p] = g_F[((size_t)p * RB + r) * NXDIM + i];

    float x = 0.f;
    __syncthreads();
    for (int c = 0; c < MBLK; c++) {
        g_Xs[((size_t)c * RB + r) * NXDIM + i] = x;
        xsh[i] = x;
        __syncthreads();
        float fv = fbuf[c & (PF - 1)];
        if (c + PF < MBLK)
            fbuf[c & (PF - 1)] = g_F[((size_t)(c + PF) * RB + r) * NXDIM + i];
        float v0 = 0.f, v1 = 0.f, v2 = 0.f, v3 = 0.f;
        #pragma unroll
        for (int j = 0; j < NXDIM; j += 4) {
            v0 += At[(j)     * NXDIM + i] * xsh[j];
            v1 += At[(j + 1) * NXDIM + i] * xsh[j + 1];
            v2 += At[(j + 2) * NXDIM + i] * xsh[j + 2];
            v3 += At[(j + 3) * NXDIM + i] * xsh[j + 3];
        }
        x = ((v0 + v1) + (v2 + v3)) + fv;
        __syncthreads();
    }
}

// ---------------------------------------------------------------------------
// Kernel 4: expansion. One CTA per block c; re-run recurrence from Xs[c],
// writing X (pre-update) and Y each step.
// ---------------------------------------------------------------------------
__global__ void __launch_bounds__(256, 2) k_expand(
    const float* __restrict__ u, const float* __restrict__ A,
    const float* __restrict__ Bu, const float* __restrict__ Cy,
    const float* __restrict__ Dyu,
    float* __restrict__ outY, float* __restrict__ outX) {
    extern __shared__ float sm[];
    float* At  = sm;                         // [j*64+i]   4096
    float* Bt  = At + NXDIM * NXDIM;         // [q*64+i]    256
    float* Csm = Bt + NUDIM * NXDIM;         // [p*64+j]    256
    float* Dsm = Csm + NYDIM * NXDIM;        // [p*4+q]      16
    float* ssh = Dsm + NYDIM * NUDIM;        // [j*128+r]  8192
    float* ush = ssh + NXDIM * RB;           // [q*128+r]   512

    int t = threadIdx.x;
    int c = blockIdx.x;
    int rb = t & 15, ib = t >> 4;
    int r0 = rb * 8, i0 = ib * 4;

    for (int idx = t; idx < NXDIM * NXDIM; idx += 256)
        At[(idx % NXDIM) * NXDIM + (idx / NXDIM)] = A[idx];
    if (t < NUDIM * NXDIM) Bt[(t % NUDIM) * NXDIM + (t / NUDIM)] = Bu[t];
    if (t < NYDIM * NXDIM) Csm[t] = Cy[t];
    if (t < NYDIM * NUDIM) Dsm[t] = Dyu[t];

    float acc[4][8];
    const float* xs = g_Xs + (size_t)c * (RB * NXDIM);
    #pragma unroll
    for (int rr = 0; rr < 8; rr++) {
        float4 v = *(const float4*)(xs + (r0 + rr) * NXDIM + i0);
        acc[0][rr] = v.x; acc[1][rr] = v.y; acc[2][rr] = v.z; acc[3][rr] = v.w;
    }
    #pragma unroll
    for (int ii = 0; ii < 4; ii++) {
        *(float4*)(ssh + (i0 + ii) * RB + r0)     = make_float4(acc[ii][0], acc[ii][1], acc[ii][2], acc[ii][3]);
        *(float4*)(ssh + (i0 + ii) * RB + r0 + 4) = make_float4(acc[ii][4], acc[ii][5], acc[ii][6], acc[ii][7]);
    }

    const float* ub = u + (size_t)c * LBLK * (NUDIM * RB);
    float2 upf = *(const float2*)(ub + t * 2);
    __syncthreads();

    int yp = t >> 7;       // 0 or 1
    int yr = t & 127;

    for (int d = 0; d < LBLK; d++) {
        ((float2*)ush)[t] = upf;
        __syncthreads();
        if (d + 1 < LBLK)
            upf = *(const float2*)(ub + (d + 1) * (NUDIM * RB) + t * 2);

        size_t k = (size_t)c * LBLK + d;

        // X_k (pre-update state)
        float* xo = outX + k * (NXDIM * RB);
        #pragma unroll
        for (int ii = 0; ii < 4; ii++) {
            *(float4*)(xo + (i0 + ii) * RB + r0)     = make_float4(acc[ii][0], acc[ii][1], acc[ii][2], acc[ii][3]);
            *(float4*)(xo + (i0 + ii) * RB + r0 + 4) = make_float4(acc[ii][4], acc[ii][5], acc[ii][6], acc[ii][7]);
        }

        // Y_k = C_y X_k + D_yu U_k   (2 outputs per thread)
        float* yo = outY + k * (NYDIM * RB);
        #pragma unroll
        for (int pp = 0; pp < 2; pp++) {
            int p = yp + 2 * pp;
            float y = Dsm[p * NUDIM + 0] * ush[0 * RB + yr]
                    + Dsm[p * NUDIM + 1] * ush[1 * RB + yr]
                    + Dsm[p * NUDIM + 2] * ush[2 * RB + yr]
                    + Dsm[p * NUDIM + 3] * ush[3 * RB + yr];
            float y0 = 0.f, y1 = 0.f, y2 = 0.f, y3 = 0.f;
            #pragma unroll
            for (int j = 0; j < NXDIM; j += 4) {
                y0 += Csm[p * NXDIM + j]     * ssh[(j)     * RB + yr];
                y1 += Csm[p * NXDIM + j + 1] * ssh[(j + 1) * RB + yr];
                y2 += Csm[p * NXDIM + j + 2] * ssh[(j + 2) * RB + yr];
                y3 += Csm[p * NXDIM + j + 3] * ssh[(j + 3) * RB + yr];
            }
            yo[p * RB + yr] = y + ((y0 + y1) + (y2 + y3));
        }

        // state update: acc = A @ s + B @ u
        #pragma unroll
        for (int ii = 0; ii < 4; ii++)
            #pragma unroll
            for (int rr = 0; rr < 8; rr++) acc[ii][rr] = 0.f;

        #pragma unroll 8
        for (int j = 0; j < NXDIM; j++) {
            float4 a  = *(const float4*)(At  + j * NXDIM + i0);
            float4 sA = *(const float4*)(ssh + j * RB + r0);
            float4 sB = *(const float4*)(ssh + j * RB + r0 + 4);
            float av[4] = {a.x, a.y, a.z, a.w};
            float sv[8] = {sA.x, sA.y, sA.z, sA.w, sB.x, sB.y, sB.z, sB.w};
            #pragma unroll
            for (int ii = 0; ii < 4; ii++)
                #pragma unroll
                for (int rr = 0; rr < 8; rr++)
                    acc[ii][rr] += av[ii] * sv[rr];
        }
        #pragma unroll
        for (int q = 0; q < NUDIM; q++) {
            float4 b  = *(const float4*)(Bt  + q * NXDIM + i0);
            float4 uA = *(const float4*)(ush + q * RB + r0);
            float4 uB = *(const float4*)(ush + q * RB + r0 + 4);
            float bv[4] = {b.x, b.y, b.z, b.w};
            float uv[8] = {uA.x, uA.y, uA.z, uA.w, uB.x, uB.y, uB.z, uB.w};
            #pragma unroll
            for (int ii = 0; ii < 4; ii++)
                #pragma unroll
                for (int rr = 0; rr < 8; rr++)
                    acc[ii][rr] += bv[ii] * uv[rr];
        }
        __syncthreads();
        #pragma unroll
        for (int ii = 0; ii < 4; ii++) {
            *(float4*)(ssh + (i0 + ii) * RB + r0)     = make_float4(acc[ii][0], acc[ii][1], acc[ii][2], acc[ii][3]);
            *(float4*)(ssh + (i0 + ii) * RB + r0 + 4) = make_float4(acc[ii][4], acc[ii][5], acc[ii][6], acc[ii][7]);
        }
    }
}

// ---------------------------------------------------------------------------
extern "C" void kernel_launch(void* const* d_in, const int* in_sizes, int n_in,
                              void* d_out, int out_size) {
    (void)in_sizes; (void)n_in; (void)out_size;
    const float* u   = (const float*)d_in[0];
    const float* A   = (const float*)d_in[1];
    const float* Bu  = (const float*)d_in[2];
    const float* Cy  = (const float*)d_in[3];
    const float* Dyu = (const float*)d_in[4];
    float* outY = (float*)d_out;
    float* outX = outY + (size_t)NSTEP * NYDIM * RB;

    const int smem_fgemm  = (128 * NXDIM + 32 * 128) * (int)sizeof(float);     // 48 KB
    const int smem_expand = (NXDIM * NXDIM + NUDIM * NXDIM + NYDIM * NXDIM +
                             NYDIM * NUDIM + NXDIM * RB + NUDIM * RB) * (int)sizeof(float); // ~52 KB

    cudaFuncSetAttribute(k_fgemm,  cudaFuncAttributeMaxDynamicSharedMemorySize, smem_fgemm);
    cudaFuncSetAttribute(k_expand, cudaFuncAttributeMaxDynamicSharedMemorySize, smem_expand);

    k_powers<<<1, 256>>>(A, Bu);
    k_fgemm<<<MBLK, 256, smem_fgemm>>>(u);
    k_scan<<<RB, 64>>>();
    k_expand<<<MBLK, 256, smem_expand>>>(u, A, Bu, Cy, Dyu, outY, outX);
}

// round 2
// speedup vs baseline: 1.0022x; 1.0022x over previous
#include <cuda_runtime.h>

// ModelBLA: linear state-space simulation.
//   X_{k+1} = A X_k + B_u U_k ;  Y_k = C_y X_k + D_yu U_k ;  X_0 = 0
// Output = (Y, X) flattened: Y[8192][4][128] then X[8192][64][128], fp32.
//
// Algorithm (exact, fp32):
//   blocks of L=32 steps, M=256 blocks
//   1) k_powers : A^32 (by squaring) and G = [A^31 B, ..., B]  (64 x 128)
//   2) k_fgemm  : f_c = G @ U_c  per block (U_c is the contiguous u slab)
//   3) k_scan   : x_{c+1} = A^32 x_c + f_c   (256 sequential steps, 128 CTAs)
//   4) k_expand : per block, re-run the 32-step recurrence from x_c,
//                 writing X (pre-update) and Y each step.

#define NSTEP 8192
#define NUDIM 4
#define RB    128
#define NXDIM 64
#define NYDIM 4
#define LBLK  32
#define MBLK  (NSTEP / LBLK)   // 256

// scratch (no allocations allowed)
__device__ float g_F [MBLK * RB * NXDIM];   // [c][r][i]  8 MB
__device__ float g_Xs[MBLK * RB * NXDIM];   // [c][r][i]  8 MB
__device__ float g_A32[NXDIM * NXDIM];
__device__ float g_G [NXDIM * (LBLK * NUDIM)];   // [i][4j+q] = (A^{L-1-j} B)[i][q]

// ---------------------------------------------------------------------------
// Kernel 1: A^32 by repeated squaring + G chain. One CTA, 256 threads.
// ---------------------------------------------------------------------------
__global__ void k_powers(const float* __restrict__ A, const float* __restrict__ Bu) {
    __shared__ float Asm[NXDIM * 65];        // padded rows (stride 65) vs bank conflicts
    __shared__ float vb[2][NXDIM * NUDIM];
    int t = threadIdx.x;                      // 256 threads

    for (int idx = t; idx < NXDIM * NXDIM; idx += 256)
        Asm[(idx / NXDIM) * 65 + (idx % NXDIM)] = A[idx];
    vb[0][t] = Bu[t];                         // NXDIM*NUDIM == 256 exactly
    __syncthreads();

    // G columns: G[i][4*(L-1-m)+q] = (A^m B)[i][q]
    int gi = t >> 2, gq = t & 3;
    int cur = 0;
    for (int m = 0; m < LBLK; m++) {
        g_G[gi * (LBLK * NUDIM) + 4 * (LBLK - 1 - m) + gq] = vb[cur][gi * NUDIM + gq];
        float s = 0.f;
        #pragma unroll 8
        for (int k = 0; k < NXDIM; k++)
            s += Asm[gi * 65 + k] * vb[cur][k * NUDIM + gq];
        vb[cur ^ 1][gi * NUDIM + gq] = s;
        cur ^= 1;
        __syncthreads();
    }

    // squarings: A -> A^2 -> A^4 -> A^8 -> A^16 -> A^32 (in place, reg-staged)
    int oi = t >> 2;
    int oj0 = (t & 3) * 16;
    for (int st = 0; st < 5; st++) {
        float accq[16];
        #pragma unroll
        for (int jj = 0; jj < 16; jj++) accq[jj] = 0.f;
        for (int k = 0; k < NXDIM; k++) {
            float a = Asm[oi * 65 + k];
            #pragma unroll
            for (int jj = 0; jj < 16; jj++)
                accq[jj] += a * Asm[k * 65 + oj0 + jj];
        }
        __syncthreads();
        #pragma unroll
        for (int jj = 0; jj < 16; jj++) Asm[oi * 65 + oj0 + jj] = accq[jj];
        __syncthreads();
    }
    for (int idx = t; idx < NXDIM * NXDIM; idx += 256)
        g_A32[idx] = Asm[(idx / NXDIM) * 65 + (idx % NXDIM)];
}

// ---------------------------------------------------------------------------
// Kernel 2: f_c = G (64x128) @ U_c (128x128).  One CTA per block c.
// ---------------------------------------------------------------------------
__global__ void __launch_bounds__(256) k_fgemm(const float* __restrict__ u) {
    extern __shared__ float sm[];
    float* Gt = sm;                      // [k][i]  128*64
    float* Ut = sm + 128 * NXDIM;        // [kk][r] 32*128 chunk
    int t = threadIdx.x;
    int c = blockIdx.x;
    int rb = t & 15, ib = t >> 4;
    int r0 = rb * 8, i0 = ib * 4;

    for (int idx = t; idx < 128 * NXDIM; idx += 256) {
        int i = idx >> 7, k = idx & 127;     // g_G layout [i][k]
        Gt[k * NXDIM + i] = g_G[idx];
    }

    float acc[4][8];
    #pragma unroll
    for (int ii = 0; ii < 4; ii++)
        #pragma unroll
        for (int rr = 0; rr < 8; rr++) acc[ii][rr] = 0.f;

    const float* ublk = u + (size_t)c * (LBLK * NUDIM * RB);   // 128x128 slab
    for (int k0 = 0; k0 < 128; k0 += 32) {
        __syncthreads();
        for (int idx = t; idx < 32 * 128; idx += 256)
            Ut[idx] = ublk[(k0 + (idx >> 7)) * 128 + (idx & 127)];
        __syncthreads();
        #pragma unroll 8
        for (int kk = 0; kk < 32; kk++) {
            float4 g  = *(const float4*)(Gt + (k0 + kk) * NXDIM + i0);
            float4 ua = *(const float4*)(Ut + kk * 128 + r0);
            float4 ub = *(const float4*)(Ut + kk * 128 + r0 + 4);
            float gv[4] = {g.x, g.y, g.z, g.w};
            float uv[8] = {ua.x, ua.y, ua.z, ua.w, ub.x, ub.y, ub.z, ub.w};
            #pragma unroll
            for (int ii = 0; ii < 4; ii++)
                #pragma unroll
                for (int rr = 0; rr < 8; rr++)
                    acc[ii][rr] += gv[ii] * uv[rr];
        }
    }
    float* f = g_F + (size_t)c * (RB * NXDIM);
    #pragma unroll
    for (int rr = 0; rr < 8; rr++) {
        float4 v = make_float4(acc[0][rr], acc[1][rr], acc[2][rr], acc[3][rr]);
        *(float4*)(f + (r0 + rr) * NXDIM + i0) = v;
    }
}

// ---------------------------------------------------------------------------
// Kernel 3: sequential scan over blocks.  One CTA per column r, 64 threads.
//   Xs[c] = x ; x = A^32 x + F[c]
// ---------------------------------------------------------------------------
__global__ void __launch_bounds__(64) k_scan() {
    __shared__ float At[NXDIM * NXDIM];   // [j][i]
    __shared__ float xsh[NXDIM];
    int r = blockIdx.x;
    int i = threadIdx.x;

    for (int idx = i; idx < NXDIM * NXDIM; idx += 64) {
        int ii = idx / NXDIM, jj = idx % NXDIM;
        At[jj * NXDIM + ii] = g_A32[idx];
    }

    const int PF = 4;
    float fbuf[PF];
    #pragma unroll
    for (int p = 0; p < PF; p++)
        fbuf[p] = g_F[((size_t)p * RB + r) * NXDIM + i];

    float x = 0.f;
    __syncthreads();
    for (int c = 0; c < MBLK; c++) {
        g_Xs[((size_t)c * RB + r) * NXDIM + i] = x;
        xsh[i] = x;
        __syncthreads();
        float fv = fbuf[c & (PF - 1)];
        if (c + PF < MBLK)
            fbuf[c & (PF - 1)] = g_F[((size_t)(c + PF) * RB + r) * NXDIM + i];
        float v0 = 0.f, v1 = 0.f, v2 = 0.f, v3 = 0.f;
        #pragma unroll
        for (int j = 0; j < NXDIM; j += 4) {
            v0 += At[(j)     * NXDIM + i] * xsh[j];
            v1 += At[(j + 1) * NXDIM + i] * xsh[j + 1];
            v2 += At[(j + 2) * NXDIM + i] * xsh[j + 2];
            v3 += At[(j + 3) * NXDIM + i] * xsh[j + 3];
        }
        x = ((v0 + v1) + (v2 + v3)) + fv;
        __syncthreads();
    }
}

// ---------------------------------------------------------------------------
// Kernel 4: expansion. One CTA per block c; re-run recurrence from Xs[c],
// writing X (pre-update) and Y each step.
// ---------------------------------------------------------------------------
__global__ void __launch_bounds__(256, 2) k_expand(
    const float* __restrict__ u, const float* __restrict__ A,
    const float* __restrict__ Bu, const float* __restrict__ Cy,
    const float* __restrict__ Dyu,
    float* __restrict__ outY, float* __restrict__ outX) {
    extern __shared__ float sm[];
    float* At  = sm;                         // [j*64+i]   4096
    float* Bt  = At + NXDIM * NXDIM;         // [q*64+i]    256
    float* Csm = Bt + NUDIM * NXDIM;         // [p*64+j]    256
    float* Dsm = Csm + NYDIM * NXDIM;        // [p*4+q]      16
    float* ssh = Dsm + NYDIM * NUDIM;        // [j*128+r]  8192
    float* ush = ssh + NXDIM * RB;           // [q*128+r]   512

    int t = threadIdx.x;
    int c = blockIdx.x;
    int rb = t & 15, ib = t >> 4;
    int r0 = rb * 8, i0 = ib * 4;

    for (int idx = t; idx < NXDIM * NXDIM; idx += 256)
        At[(idx % NXDIM) * NXDIM + (idx / NXDIM)] = A[idx];
    if (t < NUDIM * NXDIM) Bt[(t % NUDIM) * NXDIM + (t / NUDIM)] = Bu[t];
    if (t < NYDIM * NXDIM) Csm[t] = Cy[t];
    if (t < NYDIM * NUDIM) Dsm[t] = Dyu[t];

    float acc[4][8];
    const float* xs = g_Xs + (size_t)c * (RB * NXDIM);
    #pragma unroll
    for (int rr = 0; rr < 8; rr++) {
        float4 v = *(const float4*)(xs + (r0 + rr) * NXDIM + i0);
        acc[0][rr] = v.x; acc[1][rr] = v.y; acc[2][rr] = v.z; acc[3][rr] = v.w;
    }
    #pragma unroll
    for (int ii = 0; ii < 4; ii++) {
        *(float4*)(ssh + (i0 + ii) * RB + r0)     = make_float4(acc[ii][0], acc[ii][1], acc[ii][2], acc[ii][3]);
        *(float4*)(ssh + (i0 + ii) * RB + r0 + 4) = make_float4(acc[ii][4], acc[ii][5], acc[ii][6], acc[ii][7]);
    }

    const float* ub = u + (size_t)c * LBLK * (NUDIM * RB);
    float2 upf = *(const float2*)(ub + t * 2);
    __syncthreads();

    int yp = t >> 7;       // 0 or 1
    int yr = t & 127;

    for (int d = 0; d < LBLK; d++) {
        ((float2*)ush)[t] = upf;
        __syncthreads();
        if (d + 1 < LBLK)
            upf = *(const float2*)(ub + (d + 1) * (NUDIM * RB) + t * 2);

        size_t k = (size_t)c * LBLK + d;

        // X_k (pre-update state)
        float* xo = outX + k * (NXDIM * RB);
        #pragma unroll
        for (int ii = 0; ii < 4; ii++) {
            *(float4*)(xo + (i0 + ii) * RB + r0)     = make_float4(acc[ii][0], acc[ii][1], acc[ii][2], acc[ii][3]);
            *(float4*)(xo + (i0 + ii) * RB + r0 + 4) = make_float4(acc[ii][4], acc[ii][5], acc[ii][6], acc[ii][7]);
        }

        // Y_k = C_y X_k + D_yu U_k   (2 outputs per thread)
        float* yo = outY + k * (NYDIM * RB);
        #pragma unroll
        for (int pp = 0; pp < 2; pp++) {
            int p = yp + 2 * pp;
            float y = Dsm[p * NUDIM + 0] * ush[0 * RB + yr]
                    + Dsm[p * NUDIM + 1] * ush[1 * RB + yr]
                    + Dsm[p * NUDIM + 2] * ush[2 * RB + yr]
                    + Dsm[p * NUDIM + 3] * ush[3 * RB + yr];
            float y0 = 0.f, y1 = 0.f, y2 = 0.f, y3 = 0.f;
            #pragma unroll
            for (int j = 0; j < NXDIM; j += 4) {
                y0 += Csm[p * NXDIM + j]     * ssh[(j)     * RB + yr];
                y1 += Csm[p * NXDIM + j + 1] * ssh[(j + 1) * RB + yr];
                y2 += Csm[p * NXDIM + j + 2] * ssh[(j + 2) * RB + yr];
                y3 += Csm[p * NXDIM + j + 3] * ssh[(j + 3) * RB + yr];
            }
            yo[p * RB + yr] = y + ((y0 + y1) + (y2 + y3));
        }

        // state update: acc = A @ s + B @ u
        #pragma unroll
        for (int ii = 0; ii < 4; ii++)
            #pragma unroll
            for (int rr = 0; rr < 8; rr++) acc[ii][rr] = 0.f;

        #pragma unroll 8
        for (int j = 0; j < NXDIM; j++) {
            float4 a  = *(const float4*)(At  + j * NXDIM + i0);
            float4 sA = *(const float4*)(ssh + j * RB + r0);
            float4 sB = *(const float4*)(ssh + j * RB + r0 + 4);
            float av[4] = {a.x, a.y, a.z, a.w};
            float sv[8] = {sA.x, sA.y, sA.z, sA.w, sB.x, sB.y, sB.z, sB.w};
            #pragma unroll
            for (int ii = 0; ii < 4; ii++)
                #pragma unroll
                for (int rr = 0; rr < 8; rr++)
                    acc[ii][rr] += av[ii] * sv[rr];
        }
        #pragma unroll
        for (int q = 0; q < NUDIM; q++) {
            float4 b  = *(const float4*)(Bt  + q * NXDIM + i0);
            float4 uA = *(const float4*)(ush + q * RB + r0);
            float4 uB = *(const float4*)(ush + q * RB + r0 + 4);
            float bv[4] = {b.x, b.y, b.z, b.w};
            float uv[8] = {uA.x, uA.y, uA.z, uA.w, uB.x, uB.y, uB.z, uB.w};
            #pragma unroll
            for (int ii = 0; ii < 4; ii++)
                #pragma unroll
                for (int rr = 0; rr < 8; rr++)
                    acc[ii][rr] += bv[ii] * uv[rr];
        }
        __syncthreads();
        #pragma unroll
        for (int ii = 0; ii < 4; ii++) {
            *(float4*)(ssh + (i0 + ii) * RB + r0)     = make_float4(acc[ii][0], acc[ii][1], acc[ii][2], acc[ii][3]);
            *(float4*)(ssh + (i0 + ii) * RB + r0 + 4) = make_float4(acc[ii][4], acc[ii][5], acc[ii][6], acc[ii][7]);
        }
    }
}

// ---------------------------------------------------------------------------
extern "C" void kernel_launch(void* const* d_in, const int* in_sizes, int n_in,
                              void* d_out, int out_size) {
    (void)in_sizes; (void)n_in; (void)out_size;
    const float* u   = (const float*)d_in[0];
    const float* A   = (const float*)d_in[1];
    const float* Bu  = (const float*)d_in[2];
    const float* Cy  = (const float*)d_in[3];
    const float* Dyu = (const float*)d_in[4];
    float* outY = (float*)d_out;
    float* outX = outY + (size_t)NSTEP * NYDIM * RB;

    const int smem_fgemm  = (128 * NXDIM + 32 * 128) * (int)sizeof(float);     // 48 KB
    const int smem_expand = (NXDIM * NXDIM + NUDIM * NXDIM + NYDIM * NXDIM +
                             NYDIM * NUDIM + NXDIM * RB + NUDIM * RB) * (int)sizeof(float); // ~52 KB

    cudaFuncSetAttribute(k_fgemm,  cudaFuncAttributeMaxDynamicSharedMemorySize, smem_fgemm);
    cudaFuncSetAttribute(k_expand, cudaFuncAttributeMaxDynamicSharedMemorySize, smem_expand);

    k_powers<<<1, 256>>>(A, Bu);
    k_fgemm<<<MBLK, 256, smem_fgemm>>>(u);
    k_scan<<<RB, 64>>>();
    k_expand<<<MBLK, 256, smem_expand>>>(u, A, Bu, Cy, Dyu, outY, outX);
}